// round 8
// baseline (speedup 1.0000x reference)
#include <cuda_runtime.h>
#include <cstdint>
#include <math.h>

#define Hh    1024
#define Ii    512
#define TWOI  1024
#define Ee    64
#define TT    8192
#define CAPc  1024
#define KC    32
#define LDA   36
#define LDB2  264          // 256 tile cols + 8 pad

#define A_SZ  (128 * LDA)          // 4608 floats per A stage
#define B_SZ  (KC * LDB2)          // 8448 floats per B stage
#define SMEM_FLOATS (2 * A_SZ + 2 * B_SZ + 128)
#define SMEM_BYTES  (SMEM_FLOATS * 4)   // ~105 KB

// ---------------- scratch (static device globals; allocation-free) ----------
__device__ int   g_cnt[Ee];
__device__ int   g_tok[Ee * CAPc];
__device__ int   g_slot[TT * 2];
__device__ int   g_eid[TT * 2];
__device__ float g_wt[TT * 2];
__device__ float g_xn[(size_t)TT * Hh];
__device__ float g_hact[(size_t)Ee * CAPc * Ii];
__device__ float g_ybuf[(size_t)Ee * CAPc * Hh];
__device__ float g_shact[(size_t)TT * Ii];
__device__ float g_shout[(size_t)TT * Hh];

// ---------------- helpers ----------------------------------------------------
__device__ __forceinline__ uint32_t cvt_tf32(float x) {
    uint32_t r; asm("cvt.rna.tf32.f32 %0, %1;" : "=r"(r) : "f"(x)); return r;
}
__device__ __forceinline__ void mma8(float* d, const uint32_t* a, const uint32_t* b) {
    asm volatile("mma.sync.aligned.m16n8k8.row.col.f32.tf32.tf32.f32 "
                 "{%0,%1,%2,%3},{%4,%5,%6,%7},{%8,%9},{%0,%1,%2,%3};"
                 : "+f"(d[0]), "+f"(d[1]), "+f"(d[2]), "+f"(d[3])
                 : "r"(a[0]), "r"(a[1]), "r"(a[2]), "r"(a[3]), "r"(b[0]), "r"(b[1]));
}
__device__ __forceinline__ void cpa16(float* s, const void* g) {
    uint32_t sa = (uint32_t)__cvta_generic_to_shared(s);
    asm volatile("cp.async.cg.shared.global [%0], [%1], 16;" :: "r"(sa), "l"(g));
}
__device__ __forceinline__ float silu(float x) { return x / (1.f + expf(-x)); }

// ---------------- tf32 tensor-core GEMM tile: 128 rows x 256 tile cols -------
// Warp grid 2x4, warp tile 64x64. Double-buffered cp.async; dynamic smem.
// GLU: tile cols in 16 groups of (8 gate + 8 up) of the SAME 8 output cols so
// each thread's even/odd j accumulators pair g/u for the silu epilogue.
template<bool GLU, bool GATHER, int KD>
__device__ __forceinline__ void gemm_tile(
    const float* __restrict__ Asrc, int lda,
    const int* __restrict__ gtoks, int cnt, int row0,
    const float* __restrict__ Bg, const float* __restrict__ Bu, int ldb,
    float* __restrict__ C, int ldc)
{
    extern __shared__ float smem[];
    float* AsBuf[2] = { smem,            smem + A_SZ };
    float* BsBuf[2] = { smem + 2 * A_SZ, smem + 2 * A_SZ + B_SZ };
    int*   toks     = (int*)(smem + 2 * A_SZ + 2 * B_SZ);

    const int tid = threadIdx.x;
    if (GATHER) {
        if (tid < 128) toks[tid] = gtoks[min(row0 + tid, cnt - 1)];
        __syncthreads();
    }
    const int wid = tid >> 5, lane = tid & 31;
    const int wr = wid >> 2, wc = wid & 3;     // warp grid 2x4
    const int qr = lane >> 2, qc = lane & 3;   // quad row/col within warp

    // load coordinates
    const int lm  = tid >> 3, lkc = (tid & 7) << 2;    // A: base row (0..31), k-sub
    const int bk  = tid >> 6, bnc = (tid & 63) << 2;   // B: base k (0..3),  n-sub (0..252)

    // per-j A row pointers (token resolved per row!)
    const float* arow[4];
    #pragma unroll
    for (int j = 0; j < 4; j++) {
        const int m = lm + j * 32;
        arow[j] = GATHER ? Asrc + (size_t)toks[m] * lda + lkc
                         : Asrc + (size_t)(row0 + m) * lda + lkc;
    }
    const float* brow;
    if (GLU) {
        int grp = bnc >> 4, off = bnc & 15;
        brow = (off < 8) ? (Bg + grp * 8 + off) : (Bu + grp * 8 + off - 8);
        brow += (size_t)bk * ldb;
    } else {
        brow = Bg + bnc + (size_t)bk * ldb;
    }

    auto load_stage = [&](int s, int buf) {
        const int k0 = s * KC;
        float* As = AsBuf[buf];
        float* Bs = BsBuf[buf];
        #pragma unroll
        for (int j = 0; j < 4; j++)
            cpa16(&As[(lm + j * 32) * LDA + lkc], arow[j] + k0);
        #pragma unroll
        for (int j = 0; j < 8; j++)
            cpa16(&Bs[(bk + j * 4) * LDB2 + bnc], brow + (size_t)(k0 + j * 4) * ldb);
        asm volatile("cp.async.commit_group;" ::: "memory");
    };

    float acc[4][8][4];
    #pragma unroll
    for (int i = 0; i < 4; i++)
        #pragma unroll
        for (int j = 0; j < 8; j++)
            #pragma unroll
            for (int k = 0; k < 4; k++) acc[i][j][k] = 0.f;

    constexpr int S = KD / KC;
    load_stage(0, 0);

    for (int s = 0; s < S; s++) {
        const int buf = s & 1;
        if (s + 1 < S) {
            load_stage(s + 1, (s + 1) & 1);
            asm volatile("cp.async.wait_group 1;" ::: "memory");
        } else {
            asm volatile("cp.async.wait_group 0;" ::: "memory");
        }
        __syncthreads();

        const float* As = AsBuf[buf];
        const float* Bs = BsBuf[buf];
        #pragma unroll
        for (int ks = 0; ks < KC; ks += 8) {
            uint32_t af[4][4];
            #pragma unroll
            for (int i = 0; i < 4; i++) {
                int r = wr * 64 + i * 16 + qr;
                af[i][0] = cvt_tf32(As[r * LDA + ks + qc]);
                af[i][1] = cvt_tf32(As[(r + 8) * LDA + ks + qc]);
                af[i][2] = cvt_tf32(As[r * LDA + ks + qc + 4]);
                af[i][3] = cvt_tf32(As[(r + 8) * LDA + ks + qc + 4]);
            }
            #pragma unroll
            for (int j = 0; j < 8; j++) {
                uint32_t bf[2];
                int n = wc * 64 + j * 8 + qr;
                bf[0] = cvt_tf32(Bs[(ks + qc) * LDB2 + n]);
                bf[1] = cvt_tf32(Bs[(ks + qc + 4) * LDB2 + n]);
                #pragma unroll
                for (int i = 0; i < 4; i++) mma8(acc[i][j], af[i], bf);
            }
        }
        __syncthreads();   // compute done before s+2 overwrites this buffer
    }

    // ---- epilogue
    if (GLU) {
        // warp covers 32 gate + 32 up interleaved; even j = gate, odd j = up
        #pragma unroll
        for (int i = 0; i < 4; i++) {
            size_t r = (size_t)(wr * 64 + i * 16 + qr);
            #pragma unroll
            for (int jg = 0; jg < 8; jg += 2) {
                int c = wc * 32 + (jg >> 1) * 8 + 2 * qc;
                const float* g = acc[i][jg];
                const float* u = acc[i][jg + 1];
                *(float2*)(C + r * ldc + c)       = make_float2(silu(g[0]) * u[0], silu(g[1]) * u[1]);
                *(float2*)(C + (r + 8) * ldc + c) = make_float2(silu(g[2]) * u[2], silu(g[3]) * u[3]);
            }
        }
    } else {
        #pragma unroll
        for (int i = 0; i < 4; i++) {
            size_t r = (size_t)(wr * 64 + i * 16 + qr);
            #pragma unroll
            for (int j = 0; j < 8; j++) {
                int c = wc * 64 + j * 8 + 2 * qc;
                *(float2*)(C + r * ldc + c)       = make_float2(acc[i][j][0], acc[i][j][1]);
                *(float2*)(C + (r + 8) * ldc + c) = make_float2(acc[i][j][2], acc[i][j][3]);
            }
        }
    }
}

// ---------------- GEMM kernels -----------------------------------------------
__global__ void __launch_bounds__(256) k_eg1(const float* __restrict__ w13) {
    const int e = blockIdx.x;
    const int cnt = min(g_cnt[e], CAPc);
    const int row0 = blockIdx.y << 7;
    if (cnt == 0 || row0 >= cnt) return;
    const float* Bg = w13 + (size_t)e * Hh * TWOI + blockIdx.z * 128;   // gate cols
    const float* Bu = Bg + Ii;                                          // up cols
    float* C = g_hact + (size_t)e * CAPc * Ii + (size_t)row0 * Ii + blockIdx.z * 128;
    gemm_tile<true, true, Hh>(g_xn, Hh, g_tok + e * CAPc, cnt, row0, Bg, Bu, TWOI, C, Ii);
}

__global__ void __launch_bounds__(256) k_eg2(const float* __restrict__ w2) {
    const int e = blockIdx.x;
    const int cnt = min(g_cnt[e], CAPc);
    const int row0 = blockIdx.y << 7;
    if (cnt == 0 || row0 >= cnt) return;
    const float* B = w2 + (size_t)e * Ii * Hh + blockIdx.z * 256;
    float* C = g_ybuf + (size_t)e * CAPc * Hh + (size_t)row0 * Hh + blockIdx.z * 256;
    gemm_tile<false, false, Ii>(g_hact + (size_t)e * CAPc * Ii, Ii, nullptr, 0, row0,
                                B, nullptr, Hh, C, Hh);
}

__global__ void __launch_bounds__(256) k_sg1(const float* __restrict__ swg,
                                             const float* __restrict__ swu) {
    const int row0 = blockIdx.x << 7;
    const float* Bg = swg + blockIdx.y * 128;
    const float* Bu = swu + blockIdx.y * 128;
    float* C = g_shact + (size_t)row0 * Ii + blockIdx.y * 128;
    gemm_tile<true, false, Hh>(g_xn, Hh, nullptr, 0, row0, Bg, Bu, Ii, C, Ii);
}

__global__ void __launch_bounds__(256) k_sg2(const float* __restrict__ swd) {
    const int row0 = blockIdx.x << 7;
    const float* B = swd + blockIdx.y * 256;
    float* C = g_shout + (size_t)row0 * Hh + blockIdx.y * 256;
    gemm_tile<false, false, Ii>(g_shact, Ii, nullptr, 0, row0, B, nullptr, Hh, C, Hh);
}

// ---------------- kernel 0: zero expert counters ----------------------------
__global__ void k_zero() {
    if (threadIdx.x < Ee) g_cnt[threadIdx.x] = 0;
}

// ---------------- kernel 1: rmsnorm + gate logits + top2 + routing ----------
__global__ void k_rms_route(const float* __restrict__ hs,
                            const float* __restrict__ rmsw,
                            const float* __restrict__ gw) {
    __shared__ float xs[Hh];
    __shared__ float lg[Ee];
    __shared__ float red[8];
    const int t   = blockIdx.x;
    const int tid = threadIdx.x;
    const float* hrow = hs + (size_t)t * Hh;

    float ss = 0.f;
    for (int i = tid; i < Hh; i += 256) { float v = hrow[i]; xs[i] = v; ss += v * v; }
    #pragma unroll
    for (int o = 16; o; o >>= 1) ss += __shfl_xor_sync(0xffffffffu, ss, o);
    if ((tid & 31) == 0) red[tid >> 5] = ss;
    __syncthreads();
    if (tid < 8) {
        float v = red[tid];
        #pragma unroll
        for (int o = 4; o; o >>= 1) v += __shfl_xor_sync(0xffu, v, o);
        if (tid == 0) red[0] = v;
    }
    __syncthreads();
    const float scale = rsqrtf(red[0] * (1.0f / Hh) + 1e-6f);
    for (int i = tid; i < Hh; i += 256) {
        float v = xs[i] * scale * rmsw[i];
        xs[i] = v;
        g_xn[(size_t)t * Hh + i] = v;
    }
    __syncthreads();

    const int w = tid >> 5, lane = tid & 31;
    #pragma unroll
    for (int j = 0; j < 8; j++) {
        const int e = w * 8 + j;
        const float* ge = gw + (size_t)e * Hh;
        float s = 0.f;
        for (int i = lane; i < Hh; i += 32) s += xs[i] * ge[i];
        #pragma unroll
        for (int o = 16; o; o >>= 1) s += __shfl_xor_sync(0xffffffffu, s, o);
        if (lane == 0) lg[e] = s;
    }
    __syncthreads();

    if (tid == 0) {
        float l1 = -1e30f, l2 = -1e30f; int e1 = 0, e2 = 0;
        #pragma unroll
        for (int e = 0; e < Ee; e++) {
            float v = lg[e];
            if (v > l1)      { l2 = l1; e2 = e1; l1 = v; e1 = e; }
            else if (v > l2) { l2 = v;  e2 = e; }
        }
        const float w1 = 1.f / (1.f + expf(l2 - l1));
        const float w2 = 1.f - w1;
        g_eid[2 * t] = e1; g_eid[2 * t + 1] = e2;
        g_wt [2 * t] = w1; g_wt [2 * t + 1] = w2;
        int s1 = atomicAdd(&g_cnt[e1], 1);
        int s2 = atomicAdd(&g_cnt[e2], 1);
        if (s1 < CAPc) { g_tok[e1 * CAPc + s1] = t; g_slot[2 * t]     = s1; }
        else           { g_slot[2 * t]     = -1; }
        if (s2 < CAPc) { g_tok[e2 * CAPc + s2] = t; g_slot[2 * t + 1] = s2; }
        else           { g_slot[2 * t + 1] = -1; }
    }
}

// ---------------- combine: residual + shared + sum_k w*y --------------------
__global__ void k_comb(const float* __restrict__ hs, float* __restrict__ out) {
    const int t = blockIdx.x;
    const int tid = threadIdx.x;
    const int e0 = g_eid[2 * t], e1 = g_eid[2 * t + 1];
    const int s0 = g_slot[2 * t], s1 = g_slot[2 * t + 1];
    const float w0 = g_wt[2 * t], w1 = g_wt[2 * t + 1];

    const float4* r4  = (const float4*)(hs + (size_t)t * Hh);
    const float4* sh4 = (const float4*)(g_shout + (size_t)t * Hh);
    const float4* y0  = (s0 >= 0) ? (const float4*)(g_ybuf + ((size_t)e0 * CAPc + s0) * Hh) : nullptr;
    const float4* y1  = (s1 >= 0) ? (const float4*)(g_ybuf + ((size_t)e1 * CAPc + s1) * Hh) : nullptr;
    float4* o4 = (float4*)(out + (size_t)t * Hh);

    for (int i = tid; i < Hh / 4; i += 256) {
        float4 a = r4[i], b = sh4[i];
        float4 acc = make_float4(a.x + b.x, a.y + b.y, a.z + b.z, a.w + b.w);
        if (y0) { float4 y = y0[i]; acc.x += w0 * y.x; acc.y += w0 * y.y; acc.z += w0 * y.z; acc.w += w0 * y.w; }
        if (y1) { float4 y = y1[i]; acc.x += w1 * y.x; acc.y += w1 * y.y; acc.z += w1 * y.z; acc.w += w1 * y.w; }
        o4[i] = acc;
    }
}

// ---------------- launcher ---------------------------------------------------
extern "C" void kernel_launch(void* const* d_in, const int* in_sizes, int n_in,
                              void* d_out, int out_size) {
    const float* hs   = (const float*)d_in[0];
    const float* rmsw = (const float*)d_in[1];
    const float* gw   = (const float*)d_in[2];
    const float* w13  = (const float*)d_in[3];
    const float* w2   = (const float*)d_in[4];
    const float* swg  = (const float*)d_in[5];
    const float* swu  = (const float*)d_in[6];
    const float* swd  = (const float*)d_in[7];
    float* out = (float*)d_out;

    cudaFuncSetAttribute(k_eg1, cudaFuncAttributeMaxDynamicSharedMemorySize, SMEM_BYTES);
    cudaFuncSetAttribute(k_eg2, cudaFuncAttributeMaxDynamicSharedMemorySize, SMEM_BYTES);
    cudaFuncSetAttribute(k_sg1, cudaFuncAttributeMaxDynamicSharedMemorySize, SMEM_BYTES);
    cudaFuncSetAttribute(k_sg2, cudaFuncAttributeMaxDynamicSharedMemorySize, SMEM_BYTES);

    k_zero<<<1, 64>>>();
    k_rms_route<<<TT, 256>>>(hs, rmsw, gw);
    k_eg1<<<dim3(Ee, CAPc / 128, Ii / 128), 256, SMEM_BYTES>>>(w13);
    k_sg1<<<dim3(TT / 128, Ii / 128), 256, SMEM_BYTES>>>(swg, swu);
    k_eg2<<<dim3(Ee, CAPc / 128, Hh / 256), 256, SMEM_BYTES>>>(w2);
    k_sg2<<<dim3(TT / 128, Hh / 256), 256, SMEM_BYTES>>>(swd);
    k_comb<<<TT, 256>>>(hs, out);
}

// round 10
// speedup vs baseline: 1.0768x; 1.0768x over previous
#include <cuda_runtime.h>
#include <cstdint>
#include <math.h>

#define Hh    1024
#define Ii    512
#define TWOI  1024
#define Ee    64
#define TT    8192
#define CAPc  1024
#define KC    32
#define LDA   36
#define LDB   136

#define A_SZ  (128 * LDA)          // floats per A stage buffer
#define B_SZ  (KC * LDB)           // floats per B stage buffer
#define SMEM_FLOATS (2 * A_SZ + 2 * B_SZ + 128)
#define SMEM_BYTES  (SMEM_FLOATS * 4)

// ---------------- scratch (static device globals; allocation-free) ----------
__device__ int   g_cnt[Ee];
__device__ int   g_tok[Ee * CAPc];
__device__ int   g_slot[TT * 2];
__device__ int   g_eid[TT * 2];
__device__ float g_wt[TT * 2];
__device__ float g_xn[(size_t)TT * Hh];      // tf32-rounded rmsnorm output
__device__ float g_hact[(size_t)Ee * CAPc * Ii];   // tf32-rounded expert act
__device__ float g_ybuf[(size_t)Ee * CAPc * Hh];
__device__ float g_shact[(size_t)TT * Ii];   // tf32-rounded shared act
__device__ float g_shout[(size_t)TT * Hh];

// ---------------- helpers ----------------------------------------------------
__device__ __forceinline__ uint32_t cvt_tf32(float x) {
    uint32_t r; asm("cvt.rna.tf32.f32 %0, %1;" : "=r"(r) : "f"(x)); return r;
}
// round to a tf32-representable fp32 (RNA) — used at activation WRITE time so
// GEMM A-operands can be loaded raw (hw truncation of a tf32 value = identity).
__device__ __forceinline__ float round_tf32(float x) {
    return __uint_as_float(cvt_tf32(x));
}
__device__ __forceinline__ void mma8(float* d, const uint32_t* a, const uint32_t* b) {
    asm volatile("mma.sync.aligned.m16n8k8.row.col.f32.tf32.tf32.f32 "
                 "{%0,%1,%2,%3},{%4,%5,%6,%7},{%8,%9},{%0,%1,%2,%3};"
                 : "+f"(d[0]), "+f"(d[1]), "+f"(d[2]), "+f"(d[3])
                 : "r"(a[0]), "r"(a[1]), "r"(a[2]), "r"(a[3]), "r"(b[0]), "r"(b[1]));
}
__device__ __forceinline__ void cpa16(float* s, const void* g) {
    uint32_t sa = (uint32_t)__cvta_generic_to_shared(s);
    asm volatile("cp.async.cg.shared.global [%0], [%1], 16;" :: "r"(sa), "l"(g));
}
__device__ __forceinline__ float silu(float x) { return x / (1.f + expf(-x)); }

// ---------------- tf32 tensor-core GEMM tile: 128 rows x 128 tile cols -------
// Warp grid 2x4, warp tile 64x32. Double-buffered cp.async; dynamic smem.
// A operands are pre-rounded to tf32 in gmem -> raw loads, NO cvt on A path.
// B (weights) get cvt.rna in-loop. Numerics identical to full-RNA version.
// GLU: tile cols interleave gate/up in 8-col n-tiles; GLU outputs (which feed
// the next GEMM) are written tf32-rounded.
template<bool GLU, bool GATHER, int KD>
__device__ __forceinline__ void gemm_tile(
    const float* __restrict__ Asrc, int lda,
    const int* __restrict__ gtoks, int cnt, int row0,
    const float* __restrict__ Bg, const float* __restrict__ Bu, int ldb,
    float* __restrict__ C, int ldc)
{
    extern __shared__ float smem[];
    float* AsBuf[2] = { smem,            smem + A_SZ };
    float* BsBuf[2] = { smem + 2 * A_SZ, smem + 2 * A_SZ + B_SZ };
    int*   toks     = (int*)(smem + 2 * A_SZ + 2 * B_SZ);

    const int tid = threadIdx.x;
    if (GATHER) {
        if (tid < 128) toks[tid] = gtoks[min(row0 + tid, cnt - 1)];
        __syncthreads();
    }
    const int wid = tid >> 5, lane = tid & 31;
    const int wr = wid >> 2, wc = wid & 3;     // warp grid 2x4
    const int qr = lane >> 2, qc = lane & 3;   // quad row/col within warp

    // load coordinates
    const int lm  = tid >> 3, lkc = (tid & 7) << 2;    // A: base row (0..31), k-sub
    const int bk  = tid >> 5, bnc = (tid & 31) << 2;   // B: base k (0..7),  n-sub

    // per-j A row pointers (token resolved per row)
    const float* arow[4];
    #pragma unroll
    for (int j = 0; j < 4; j++) {
        const int m = lm + j * 32;
        arow[j] = GATHER ? Asrc + (size_t)toks[m] * lda + lkc
                         : Asrc + (size_t)(row0 + m) * lda + lkc;
    }
    const float* brow;
    if (GLU) {
        int grp = bnc >> 4, off = bnc & 15;
        brow = (off < 8) ? (Bg + grp * 8 + off) : (Bu + grp * 8 + off - 8);
        brow += (size_t)bk * ldb;
    } else {
        brow = Bg + bnc + (size_t)bk * ldb;
    }

    auto load_stage = [&](int s, int buf) {
        const int k0 = s * KC;
        float* As = AsBuf[buf];
        float* Bs = BsBuf[buf];
        #pragma unroll
        for (int j = 0; j < 4; j++)
            cpa16(&As[(lm + j * 32) * LDA + lkc], arow[j] + k0);
        #pragma unroll
        for (int j = 0; j < 4; j++)
            cpa16(&Bs[(bk + j * 8) * LDB + bnc], brow + (size_t)(k0 + j * 8) * ldb);
        asm volatile("cp.async.commit_group;" ::: "memory");
    };

    float acc[4][4][4];
    #pragma unroll
    for (int i = 0; i < 4; i++)
        #pragma unroll
        for (int j = 0; j < 4; j++)
            #pragma unroll
            for (int k = 0; k < 4; k++) acc[i][j][k] = 0.f;

    constexpr int S = KD / KC;
    load_stage(0, 0);

    for (int s = 0; s < S; s++) {
        const int buf = s & 1;
        if (s + 1 < S) {
            load_stage(s + 1, (s + 1) & 1);
            asm volatile("cp.async.wait_group 1;" ::: "memory");
        } else {
            asm volatile("cp.async.wait_group 0;" ::: "memory");
        }
        __syncthreads();

        const uint32_t* As = (const uint32_t*)AsBuf[buf];
        const float*    Bs = BsBuf[buf];
        #pragma unroll
        for (int ks = 0; ks < KC; ks += 8) {
            uint32_t af[4][4], bf[4][2];
            #pragma unroll
            for (int i = 0; i < 4; i++) {
                int r = wr * 64 + i * 16 + qr;
                af[i][0] = As[r * LDA + ks + qc];          // raw: pre-rounded tf32
                af[i][1] = As[(r + 8) * LDA + ks + qc];
                af[i][2] = As[r * LDA + ks + qc + 4];
                af[i][3] = As[(r + 8) * LDA + ks + qc + 4];
            }
            #pragma unroll
            for (int j = 0; j < 4; j++) {
                int n = wc * 32 + j * 8 + qr;
                bf[j][0] = cvt_tf32(Bs[(ks + qc) * LDB + n]);      // weights: RNA
                bf[j][1] = cvt_tf32(Bs[(ks + qc + 4) * LDB + n]);
            }
            #pragma unroll
            for (int i = 0; i < 4; i++)
                #pragma unroll
                for (int j = 0; j < 4; j++) mma8(acc[i][j], af[i], bf[j]);
        }
        __syncthreads();   // compute done before s+2 overwrites this buffer
    }

    // ---- epilogue
    if (GLU) {
        // GLU outputs feed the next GEMM -> write tf32-rounded values
        #pragma unroll
        for (int i = 0; i < 4; i++) {
            size_t r = (size_t)(wr * 64 + i * 16 + qr);
            #pragma unroll
            for (int jg = 0; jg < 4; jg += 2) {
                int c = (wc * 2 + (jg >> 1)) * 8 + 2 * qc;
                const float* g = acc[i][jg];
                const float* u = acc[i][jg + 1];
                *(float2*)(C + r * ldc + c) =
                    make_float2(round_tf32(silu(g[0]) * u[0]), round_tf32(silu(g[1]) * u[1]));
                *(float2*)(C + (r + 8) * ldc + c) =
                    make_float2(round_tf32(silu(g[2]) * u[2]), round_tf32(silu(g[3]) * u[3]));
            }
        }
    } else {
        #pragma unroll
        for (int i = 0; i < 4; i++) {
            size_t r = (size_t)(wr * 64 + i * 16 + qr);
            #pragma unroll
            for (int j = 0; j < 4; j++) {
                int c = (wc * 4 + j) * 8 + 2 * qc;
                *(float2*)(C + r * ldc + c)       = make_float2(acc[i][j][0], acc[i][j][1]);
                *(float2*)(C + (r + 8) * ldc + c) = make_float2(acc[i][j][2], acc[i][j][3]);
            }
        }
    }
}

// ---------------- GEMM kernels -----------------------------------------------
__global__ void __launch_bounds__(256, 2) k_eg1(const float* __restrict__ w13) {
    const int e = blockIdx.x;
    const int cnt = min(g_cnt[e], CAPc);
    const int row0 = blockIdx.y << 7;
    if (cnt == 0 || row0 >= cnt) return;
    const float* Bg = w13 + (size_t)e * Hh * TWOI + blockIdx.z * 64;
    const float* Bu = Bg + Ii;
    float* C = g_hact + (size_t)e * CAPc * Ii + (size_t)row0 * Ii + blockIdx.z * 64;
    gemm_tile<true, true, Hh>(g_xn, Hh, g_tok + e * CAPc, cnt, row0, Bg, Bu, TWOI, C, Ii);
}

__global__ void __launch_bounds__(256, 2) k_eg2(const float* __restrict__ w2) {
    const int e = blockIdx.x;
    const int cnt = min(g_cnt[e], CAPc);
    const int row0 = blockIdx.y << 7;
    if (cnt == 0 || row0 >= cnt) return;
    const float* B = w2 + (size_t)e * Ii * Hh + blockIdx.z * 128;
    float* C = g_ybuf + (size_t)e * CAPc * Hh + (size_t)row0 * Hh + blockIdx.z * 128;
    gemm_tile<false, false, Ii>(g_hact + (size_t)e * CAPc * Ii, Ii, nullptr, 0, row0,
                                B, nullptr, Hh, C, Hh);
}

__global__ void __launch_bounds__(256, 2) k_sg1(const float* __restrict__ swg,
                                                const float* __restrict__ swu) {
    const int row0 = blockIdx.x << 7;
    const float* Bg = swg + blockIdx.y * 64;
    const float* Bu = swu + blockIdx.y * 64;
    float* C = g_shact + (size_t)row0 * Ii + blockIdx.y * 64;
    gemm_tile<true, false, Hh>(g_xn, Hh, nullptr, 0, row0, Bg, Bu, Ii, C, Ii);
}

__global__ void __launch_bounds__(256, 2) k_sg2(const float* __restrict__ swd) {
    const int row0 = blockIdx.x << 7;
    const float* B = swd + blockIdx.y * 128;
    float* C = g_shout + (size_t)row0 * Hh + blockIdx.y * 128;
    gemm_tile<false, false, Ii>(g_shact, Ii, nullptr, 0, row0, B, nullptr, Hh, C, Hh);
}

// ---------------- kernel 0: zero expert counters ----------------------------
__global__ void k_zero() {
    if (threadIdx.x < Ee) g_cnt[threadIdx.x] = 0;
}

// ---------------- kernel 1: rmsnorm + gate logits + top2 + routing ----------
__global__ void k_rms_route(const float* __restrict__ hs,
                            const float* __restrict__ rmsw,
                            const float* __restrict__ gw) {
    __shared__ float xs[Hh];
    __shared__ float lg[Ee];
    __shared__ float red[8];
    const int t   = blockIdx.x;
    const int tid = threadIdx.x;
    const float* hrow = hs + (size_t)t * Hh;

    float ss = 0.f;
    for (int i = tid; i < Hh; i += 256) { float v = hrow[i]; xs[i] = v; ss += v * v; }
    #pragma unroll
    for (int o = 16; o; o >>= 1) ss += __shfl_xor_sync(0xffffffffu, ss, o);
    if ((tid & 31) == 0) red[tid >> 5] = ss;
    __syncthreads();
    if (tid < 8) {
        float v = red[tid];
        #pragma unroll
        for (int o = 4; o; o >>= 1) v += __shfl_xor_sync(0xffu, v, o);
        if (tid == 0) red[0] = v;
    }
    __syncthreads();
    const float scale = rsqrtf(red[0] * (1.0f / Hh) + 1e-6f);
    for (int i = tid; i < Hh; i += 256) {
        float v = xs[i] * scale * rmsw[i];
        xs[i] = v;                                   // full fp32 for gate logits
        g_xn[(size_t)t * Hh + i] = round_tf32(v);    // tf32-rounded for GEMMs
    }
    __syncthreads();

    const int w = tid >> 5, lane = tid & 31;
    #pragma unroll
    for (int j = 0; j < 8; j++) {
        const int e = w * 8 + j;
        const float* ge = gw + (size_t)e * Hh;
        float s = 0.f;
        for (int i = lane; i < Hh; i += 32) s += xs[i] * ge[i];
        #pragma unroll
        for (int o = 16; o; o >>= 1) s += __shfl_xor_sync(0xffffffffu, s, o);
        if (lane == 0) lg[e] = s;
    }
    __syncthreads();

    if (tid == 0) {
        float l1 = -1e30f, l2 = -1e30f; int e1 = 0, e2 = 0;
        #pragma unroll
        for (int e = 0; e < Ee; e++) {
            float v = lg[e];
            if (v > l1)      { l2 = l1; e2 = e1; l1 = v; e1 = e; }
            else if (v > l2) { l2 = v;  e2 = e; }
        }
        const float w1 = 1.f / (1.f + expf(l2 - l1));
        const float w2 = 1.f - w1;
        g_eid[2 * t] = e1; g_eid[2 * t + 1] = e2;
        g_wt [2 * t] = w1; g_wt [2 * t + 1] = w2;
        int s1 = atomicAdd(&g_cnt[e1], 1);
        int s2 = atomicAdd(&g_cnt[e2], 1);
        if (s1 < CAPc) { g_tok[e1 * CAPc + s1] = t; g_slot[2 * t]     = s1; }
        else           { g_slot[2 * t]     = -1; }
        if (s2 < CAPc) { g_tok[e2 * CAPc + s2] = t; g_slot[2 * t + 1] = s2; }
        else           { g_slot[2 * t + 1] = -1; }
    }
}

// ---------------- combine: residual + shared + sum_k w*y --------------------
__global__ void k_comb(const float* __restrict__ hs, float* __restrict__ out) {
    const int t = blockIdx.x;
    const int tid = threadIdx.x;
    const int e0 = g_eid[2 * t], e1 = g_eid[2 * t + 1];
    const int s0 = g_slot[2 * t], s1 = g_slot[2 * t + 1];
    const float w0 = g_wt[2 * t], w1 = g_wt[2 * t + 1];

    const float4* r4  = (const float4*)(hs + (size_t)t * Hh);
    const float4* sh4 = (const float4*)(g_shout + (size_t)t * Hh);
    const float4* y0  = (s0 >= 0) ? (const float4*)(g_ybuf + ((size_t)e0 * CAPc + s0) * Hh) : nullptr;
    const float4* y1  = (s1 >= 0) ? (const float4*)(g_ybuf + ((size_t)e1 * CAPc + s1) * Hh) : nullptr;
    float4* o4 = (float4*)(out + (size_t)t * Hh);

    for (int i = tid; i < Hh / 4; i += 256) {
        float4 a = r4[i], b = sh4[i];
        float4 acc = make_float4(a.x + b.x, a.y + b.y, a.z + b.z, a.w + b.w);
        if (y0) { float4 y = y0[i]; acc.x += w0 * y.x; acc.y += w0 * y.y; acc.z += w0 * y.z; acc.w += w0 * y.w; }
        if (y1) { float4 y = y1[i]; acc.x += w1 * y.x; acc.y += w1 * y.y; acc.z += w1 * y.z; acc.w += w1 * y.w; }
        o4[i] = acc;
    }
}

// ---------------- launcher ---------------------------------------------------
extern "C" void kernel_launch(void* const* d_in, const int* in_sizes, int n_in,
                              void* d_out, int out_size) {
    const float* hs   = (const float*)d_in[0];
    const float* rmsw = (const float*)d_in[1];
    const float* gw   = (const float*)d_in[2];
    const float* w13  = (const float*)d_in[3];
    const float* w2   = (const float*)d_in[4];
    const float* swg  = (const float*)d_in[5];
    const float* swu  = (const float*)d_in[6];
    const float* swd  = (const float*)d_in[7];
    float* out = (float*)d_out;

    cudaFuncSetAttribute(k_eg1, cudaFuncAttributeMaxDynamicSharedMemorySize, SMEM_BYTES);
    cudaFuncSetAttribute(k_eg2, cudaFuncAttributeMaxDynamicSharedMemorySize, SMEM_BYTES);
    cudaFuncSetAttribute(k_sg1, cudaFuncAttributeMaxDynamicSharedMemorySize, SMEM_BYTES);
    cudaFuncSetAttribute(k_sg2, cudaFuncAttributeMaxDynamicSharedMemorySize, SMEM_BYTES);

    k_zero<<<1, 64>>>();
    k_rms_route<<<TT, 256>>>(hs, rmsw, gw);
    k_eg1<<<dim3(Ee, CAPc / 128, Ii / 64), 256, SMEM_BYTES>>>(w13);
    k_sg1<<<dim3(TT / 128, Ii / 64), 256, SMEM_BYTES>>>(swg, swu);
    k_eg2<<<dim3(Ee, CAPc / 128, Hh / 128), 256, SMEM_BYTES>>>(w2);
    k_sg2<<<dim3(TT / 128, Hh / 128), 256, SMEM_BYTES>>>(swd);
    k_comb<<<TT, 256>>>(hs, out);
}

// round 12
// speedup vs baseline: 1.3922x; 1.2929x over previous
#include <cuda_runtime.h>
#include <cuda_fp16.h>
#include <cstdint>
#include <math.h>

#define Hh    1024
#define Ii    512
#define TWOI  1024
#define Ee    64
#define TT    8192
#define CAPc  1024
#define KC    64                   // k halves per stage
#define LDAh  72                   // A smem stride (halves): 64 + 8 pad
#define LDBh  136                  // B smem stride (halves): 128 + 8 pad

#define A_BYTES (128 * LDAh * 2)   // 18432
#define B_BYTES (KC * LDBh * 2)    // 17408
#define SMEM_MAIN (2 * A_BYTES + 2 * B_BYTES)   // 71680
#define SMEM_T  (SMEM_MAIN + 1024)

// ---------------- scratch (static device globals; allocation-free) ----------
__device__ int    g_cnt[Ee];
__device__ int    g_tok[Ee * CAPc];
__device__ int    g_slot[TT * 2];
__device__ int    g_eid[TT * 2];
__device__ float  g_wt[TT * 2];
__device__ __half g_xnh[(size_t)TT * Hh];              // fp16 rmsnorm out
__device__ __half g_hacth[(size_t)Ee * CAPc * Ii];     // fp16 expert act
__device__ __half g_shacth[(size_t)TT * Ii];           // fp16 shared act
__device__ float  g_ybuf[(size_t)Ee * CAPc * Hh];      // fp32 expert out
__device__ float  g_shout[(size_t)TT * Hh];            // fp32 shared out
// fp16 weight copies (one conversion pass per launch)
__device__ __half g_w13h[(size_t)Ee * Hh * TWOI];      // 128 MB
__device__ __half g_w2h[(size_t)Ee * Ii * Hh];         // 64 MB
__device__ __half g_swgh[(size_t)Hh * Ii];
__device__ __half g_swuh[(size_t)Hh * Ii];
__device__ __half g_swdh[(size_t)Ii * Hh];

// ---------------- helpers ----------------------------------------------------
__device__ __forceinline__ float silu(float x) { return x / (1.f + expf(-x)); }
__device__ __forceinline__ void cpa16(uint32_t s, const void* g) {
    asm volatile("cp.async.cg.shared.global [%0], [%1], 16;" :: "r"(s), "l"(g));
}
__device__ __forceinline__ void mma16(float* d, const uint32_t* a, uint32_t b0, uint32_t b1) {
    asm volatile("mma.sync.aligned.m16n8k16.row.col.f32.f16.f16.f32 "
                 "{%0,%1,%2,%3},{%4,%5,%6,%7},{%8,%9},{%0,%1,%2,%3};"
                 : "+f"(d[0]), "+f"(d[1]), "+f"(d[2]), "+f"(d[3])
                 : "r"(a[0]), "r"(a[1]), "r"(a[2]), "r"(a[3]), "r"(b0), "r"(b1));
}
#define LDSM_X4(r, addr) \
    asm volatile("ldmatrix.sync.aligned.m8n8.x4.shared.b16 {%0,%1,%2,%3}, [%4];" \
                 : "=r"((r)[0]), "=r"((r)[1]), "=r"((r)[2]), "=r"((r)[3]) : "r"(addr))
#define LDSM_X4T(r, addr) \
    asm volatile("ldmatrix.sync.aligned.m8n8.x4.trans.shared.b16 {%0,%1,%2,%3}, [%4];" \
                 : "=r"((r)[0]), "=r"((r)[1]), "=r"((r)[2]), "=r"((r)[3]) : "r"(addr))

// ---------------- fp16 tensor GEMM tile: 128 rows x 128 B-tile cols ----------
// Warp grid 2x4, warp tile 64x32. A row-major [128 x KC] halves; B [KC x 128]
// halves (n contiguous) read via ldmatrix.trans. Double-buffered cp.async.
// GLU: B-tile cols interleave gate/up in 8-col groups (chunk even=gate,
// odd=up of the SAME 8 output cols); epilogue writes fp16 silu(g)*u.
template<bool GLU, bool GATHER, int KD>
__device__ __forceinline__ void hgemm_tile(
    const __half* __restrict__ Asrc, int lda,
    const int* __restrict__ gtoks, int cnt, int row0,
    const __half* __restrict__ Bg, const __half* __restrict__ Bu, int ldb,
    void* __restrict__ Cout, int ldc)
{
    extern __shared__ __align__(128) char smem[];
    const uint32_t sb = (uint32_t)__cvta_generic_to_shared(smem);
    int* toks = (int*)(smem + SMEM_MAIN);

    const int tid = threadIdx.x;
    if (GATHER) {
        if (tid < 128) toks[tid] = gtoks[min(row0 + tid, cnt - 1)];
        __syncthreads();
    }
    const int wid = tid >> 5, lane = tid & 31;
    const int wr = wid >> 2, wc = wid & 3;     // warp grid 2x4
    const int qr = lane >> 2, qc = lane & 3;

    // ---- load geometry
    const int arow = tid & 127, ahalf = tid >> 7;      // A: row, 32-half group
    const int bkrow = tid >> 2, bchk0 = tid & 3;       // B: k-row, chunk base
    const int atokr = GATHER ? toks[arow] : (row0 + arow);
    const __half* aptr = Asrc + (size_t)atokr * lda + ahalf * 32;
    const uint32_t asoff = (uint32_t)(arow * LDAh + ahalf * 32) * 2;

    const __half* bptr[4]; uint32_t bsoff[4];
    #pragma unroll
    for (int t = 0; t < 4; t++) {
        const int chunk = bchk0 + t * 4;               // 0..15, 8 halves each
        const __half* base;
        if (GLU) base = ((chunk & 1) ? Bu : Bg) + (chunk >> 1) * 8;
        else     base = Bg + chunk * 8;
        bptr[t]  = base + (size_t)bkrow * ldb;
        bsoff[t] = (uint32_t)(bkrow * LDBh + chunk * 8) * 2;
    }

    auto load_stage = [&](int s, int buf) {
        const int k0 = s * KC;
        const uint32_t ab = sb + buf * A_BYTES;
        const uint32_t bb = sb + 2 * A_BYTES + buf * B_BYTES;
        #pragma unroll
        for (int t = 0; t < 4; t++)
            cpa16(ab + asoff + t * 16, aptr + k0 + t * 8);
        #pragma unroll
        for (int t = 0; t < 4; t++)
            cpa16(bb + bsoff[t], bptr[t] + (size_t)k0 * ldb);
        asm volatile("cp.async.commit_group;" ::: "memory");
    };

    // ldmatrix per-lane base offsets (bytes)
    const uint32_t aLoff = (uint32_t)((wr * 64 + (lane & 15)) * LDAh + (lane >> 4) * 8) * 2;
    const uint32_t bLoff = (uint32_t)((lane & 15) * LDBh + wc * 32 + (lane >> 4) * 8) * 2;

    float acc[4][4][4];
    #pragma unroll
    for (int i = 0; i < 4; i++)
        #pragma unroll
        for (int j = 0; j < 4; j++)
            #pragma unroll
            for (int k = 0; k < 4; k++) acc[i][j][k] = 0.f;

    constexpr int S = KD / KC;
    load_stage(0, 0);

    for (int s = 0; s < S; s++) {
        const int buf = s & 1;
        if (s + 1 < S) {
            load_stage(s + 1, (s + 1) & 1);
            asm volatile("cp.async.wait_group 1;" ::: "memory");
        } else {
            asm volatile("cp.async.wait_group 0;" ::: "memory");
        }
        __syncthreads();

        const uint32_t aab = sb + buf * A_BYTES + aLoff;
        const uint32_t bab = sb + 2 * A_BYTES + buf * B_BYTES + bLoff;
        #pragma unroll
        for (int t = 0; t < 4; t++) {                  // k16 steps
            uint32_t af[4][4], bf[2][4];
            #pragma unroll
            for (int i = 0; i < 4; i++)
                LDSM_X4(af[i], aab + i * (16 * LDAh * 2) + t * 32);
            #pragma unroll
            for (int p = 0; p < 2; p++)
                LDSM_X4T(bf[p], bab + p * 32 + t * (16 * LDBh * 2));
            #pragma unroll
            for (int i = 0; i < 4; i++)
                #pragma unroll
                for (int j = 0; j < 4; j++)
                    mma16(acc[i][j], af[i], bf[j >> 1][(j & 1) * 2], bf[j >> 1][(j & 1) * 2 + 1]);
        }
        __syncthreads();
    }

    // ---- epilogue
    if (GLU) {
        __half* C = (__half*)Cout;
        #pragma unroll
        for (int i = 0; i < 4; i++) {
            size_t r = (size_t)(wr * 64 + i * 16 + qr);
            #pragma unroll
            for (int jg = 0; jg < 4; jg += 2) {
                int c = (wc * 2 + (jg >> 1)) * 8 + 2 * qc;
                const float* g = acc[i][jg];
                const float* u = acc[i][jg + 1];
                *(__half2*)(C + r * ldc + c) =
                    __floats2half2_rn(silu(g[0]) * u[0], silu(g[1]) * u[1]);
                *(__half2*)(C + (r + 8) * ldc + c) =
                    __floats2half2_rn(silu(g[2]) * u[2], silu(g[3]) * u[3]);
            }
        }
    } else {
        float* C = (float*)Cout;
        #pragma unroll
        for (int i = 0; i < 4; i++) {
            size_t r = (size_t)(wr * 64 + i * 16 + qr);
            #pragma unroll
            for (int j = 0; j < 4; j++) {
                int c = (wc * 4 + j) * 8 + 2 * qc;
                *(float2*)(C + r * ldc + c)       = make_float2(acc[i][j][0], acc[i][j][1]);
                *(float2*)(C + (r + 8) * ldc + c) = make_float2(acc[i][j][2], acc[i][j][3]);
            }
        }
    }
}

// ---------------- GEMM kernels -----------------------------------------------
__global__ void __launch_bounds__(256, 2) k_eg1() {
    const int e = blockIdx.x;
    const int cnt = min(g_cnt[e], CAPc);
    const int row0 = blockIdx.y << 7;
    if (cnt == 0 || row0 >= cnt) return;
    const int col0 = blockIdx.z * 64;
    const __half* Bg = g_w13h + (size_t)e * Hh * TWOI + col0;
    const __half* Bu = Bg + Ii;
    __half* C = g_hacth + (size_t)e * CAPc * Ii + (size_t)row0 * Ii + col0;
    hgemm_tile<true, true, Hh>(g_xnh, Hh, g_tok + e * CAPc, cnt, row0, Bg, Bu, TWOI, C, Ii);
}

__global__ void __launch_bounds__(256, 2) k_eg2() {
    const int e = blockIdx.x;
    const int cnt = min(g_cnt[e], CAPc);
    const int row0 = blockIdx.y << 7;
    if (cnt == 0 || row0 >= cnt) return;
    const int col0 = blockIdx.z * 128;
    const __half* B = g_w2h + (size_t)e * Ii * Hh + col0;
    float* C = g_ybuf + (size_t)e * CAPc * Hh + (size_t)row0 * Hh + col0;
    hgemm_tile<false, false, Ii>(g_hacth + (size_t)e * CAPc * Ii, Ii, nullptr, 0, row0,
                                 B, nullptr, Hh, C, Hh);
}

__global__ void __launch_bounds__(256, 2) k_sg1() {
    const int row0 = blockIdx.x << 7;
    const int col0 = blockIdx.y * 64;
    __half* C = g_shacth + (size_t)row0 * Ii + col0;
    hgemm_tile<true, false, Hh>(g_xnh, Hh, nullptr, 0, row0,
                                g_swgh + col0, g_swuh + col0, Ii, C, Ii);
}

__global__ void __launch_bounds__(256, 2) k_sg2() {
    const int row0 = blockIdx.x << 7;
    const int col0 = blockIdx.y * 128;
    float* C = g_shout + (size_t)row0 * Hh + col0;
    hgemm_tile<false, false, Ii>(g_shacth, Ii, nullptr, 0, row0,
                                 g_swdh + col0, nullptr, Hh, C, Hh);
}

// ---------------- weight fp32 -> fp16 conversion -----------------------------
__global__ void k_hconv(const float* __restrict__ src, __half* __restrict__ dst, int n4) {
    int i = blockIdx.x * blockDim.x + threadIdx.x;
    const int stride = gridDim.x * blockDim.x;
    const float4* s4 = (const float4*)src;
    __half2* d2 = (__half2*)dst;
    for (; i < n4; i += stride) {
        float4 v = s4[i];
        d2[2 * i]     = __floats2half2_rn(v.x, v.y);
        d2[2 * i + 1] = __floats2half2_rn(v.z, v.w);
    }
}

// ---------------- kernel 0: zero expert counters ----------------------------
__global__ void k_zero() {
    if (threadIdx.x < Ee) g_cnt[threadIdx.x] = 0;
}

// ---------------- kernel 1: rmsnorm + gate logits + top2 + routing ----------
__global__ void k_rms_route(const float* __restrict__ hs,
                            const float* __restrict__ rmsw,
                            const float* __restrict__ gw) {
    __shared__ float xs[Hh];
    __shared__ float lg[Ee];
    __shared__ float red[8];
    const int t   = blockIdx.x;
    const int tid = threadIdx.x;
    const float* hrow = hs + (size_t)t * Hh;

    float ss = 0.f;
    for (int i = tid; i < Hh; i += 256) { float v = hrow[i]; xs[i] = v; ss += v * v; }
    #pragma unroll
    for (int o = 16; o; o >>= 1) ss += __shfl_xor_sync(0xffffffffu, ss, o);
    if ((tid & 31) == 0) red[tid >> 5] = ss;
    __syncthreads();
    if (tid < 8) {
        float v = red[tid];
        #pragma unroll
        for (int o = 4; o; o >>= 1) v += __shfl_xor_sync(0xffu, v, o);
        if (tid == 0) red[0] = v;
    }
    __syncthreads();
    const float scale = rsqrtf(red[0] * (1.0f / Hh) + 1e-6f);
    for (int i = tid; i < Hh; i += 256) {
        float v = xs[i] * scale * rmsw[i];
        xs[i] = v;                                         // fp32 for gate logits
        g_xnh[(size_t)t * Hh + i] = __float2half_rn(v);    // fp16 for GEMMs
    }
    __syncthreads();

    const int w = tid >> 5, lane = tid & 31;
    #pragma unroll
    for (int j = 0; j < 8; j++) {
        const int e = w * 8 + j;
        const float* ge = gw + (size_t)e * Hh;
        float s = 0.f;
        for (int i = lane; i < Hh; i += 32) s += xs[i] * ge[i];
        #pragma unroll
        for (int o = 16; o; o >>= 1) s += __shfl_xor_sync(0xffffffffu, s, o);
        if (lane == 0) lg[e] = s;
    }
    __syncthreads();

    if (tid == 0) {
        float l1 = -1e30f, l2 = -1e30f; int e1 = 0, e2 = 0;
        #pragma unroll
        for (int e = 0; e < Ee; e++) {
            float v = lg[e];
            if (v > l1)      { l2 = l1; e2 = e1; l1 = v; e1 = e; }
            else if (v > l2) { l2 = v;  e2 = e; }
        }
        const float w1 = 1.f / (1.f + expf(l2 - l1));
        const float w2 = 1.f - w1;
        g_eid[2 * t] = e1; g_eid[2 * t + 1] = e2;
        g_wt [2 * t] = w1; g_wt [2 * t + 1] = w2;
        int s1 = atomicAdd(&g_cnt[e1], 1);
        int s2 = atomicAdd(&g_cnt[e2], 1);
        if (s1 < CAPc) { g_tok[e1 * CAPc + s1] = t; g_slot[2 * t]     = s1; }
        else           { g_slot[2 * t]     = -1; }
        if (s2 < CAPc) { g_tok[e2 * CAPc + s2] = t; g_slot[2 * t + 1] = s2; }
        else           { g_slot[2 * t + 1] = -1; }
    }
}

// ---------------- combine: residual + shared + sum_k w*y --------------------
__global__ void k_comb(const float* __restrict__ hs, float* __restrict__ out) {
    const int t = blockIdx.x;
    const int tid = threadIdx.x;
    const int e0 = g_eid[2 * t], e1 = g_eid[2 * t + 1];
    const int s0 = g_slot[2 * t], s1 = g_slot[2 * t + 1];
    const float w0 = g_wt[2 * t], w1 = g_wt[2 * t + 1];

    const float4* r4  = (const float4*)(hs + (size_t)t * Hh);
    const float4* sh4 = (const float4*)(g_shout + (size_t)t * Hh);
    const float4* y0  = (s0 >= 0) ? (const float4*)(g_ybuf + ((size_t)e0 * CAPc + s0) * Hh) : nullptr;
    const float4* y1  = (s1 >= 0) ? (const float4*)(g_ybuf + ((size_t)e1 * CAPc + s1) * Hh) : nullptr;
    float4* o4 = (float4*)(out + (size_t)t * Hh);

    for (int i = tid; i < Hh / 4; i += 256) {
        float4 a = r4[i], b = sh4[i];
        float4 acc = make_float4(a.x + b.x, a.y + b.y, a.z + b.z, a.w + b.w);
        if (y0) { float4 y = y0[i]; acc.x += w0 * y.x; acc.y += w0 * y.y; acc.z += w0 * y.z; acc.w += w0 * y.w; }
        if (y1) { float4 y = y1[i]; acc.x += w1 * y.x; acc.y += w1 * y.y; acc.z += w1 * y.z; acc.w += w1 * y.w; }
        o4[i] = acc;
    }
}

// ---------------- launcher ---------------------------------------------------
extern "C" void kernel_launch(void* const* d_in, const int* in_sizes, int n_in,
                              void* d_out, int out_size) {
    const float* hs   = (const float*)d_in[0];
    const float* rmsw = (const float*)d_in[1];
    const float* gw   = (const float*)d_in[2];
    const float* w13  = (const float*)d_in[3];
    const float* w2   = (const float*)d_in[4];
    const float* swg  = (const float*)d_in[5];
    const float* swu  = (const float*)d_in[6];
    const float* swd  = (const float*)d_in[7];
    float* out = (float*)d_out;

    cudaFuncSetAttribute(k_eg1, cudaFuncAttributeMaxDynamicSharedMemorySize, SMEM_T);
    cudaFuncSetAttribute(k_eg2, cudaFuncAttributeMaxDynamicSharedMemorySize, SMEM_T);
    cudaFuncSetAttribute(k_sg1, cudaFuncAttributeMaxDynamicSharedMemorySize, SMEM_T);
    cudaFuncSetAttribute(k_sg2, cudaFuncAttributeMaxDynamicSharedMemorySize, SMEM_T);

    __half* w13h; __half* w2h; __half* swgh; __half* swuh; __half* swdh;
    cudaGetSymbolAddress((void**)&w13h, g_w13h);
    cudaGetSymbolAddress((void**)&w2h,  g_w2h);
    cudaGetSymbolAddress((void**)&swgh, g_swgh);
    cudaGetSymbolAddress((void**)&swuh, g_swuh);
    cudaGetSymbolAddress((void**)&swdh, g_swdh);

    k_hconv<<<4096, 256>>>(w13, w13h, Ee * Hh * TWOI / 4);
    k_hconv<<<4096, 256>>>(w2,  w2h,  Ee * Ii * Hh / 4);
    k_hconv<<<512, 256>>>(swg, swgh, Hh * Ii / 4);
    k_hconv<<<512, 256>>>(swu, swuh, Hh * Ii / 4);
    k_hconv<<<512, 256>>>(swd, swdh, Ii * Hh / 4);

    k_zero<<<1, 64>>>();
    k_rms_route<<<TT, 256>>>(hs, rmsw, gw);
    k_eg1<<<dim3(Ee, CAPc / 128, Ii / 64), 256, SMEM_T>>>();
    k_sg1<<<dim3(TT / 128, Ii / 64), 256, SMEM_T>>>();
    k_eg2<<<dim3(Ee, CAPc / 128, Hh / 128), 256, SMEM_T>>>();
    k_sg2<<<dim3(TT / 128, Hh / 128), 256, SMEM_T>>>();
    k_comb<<<TT, 256>>>(hs, out);
}